// round 5
// baseline (speedup 1.0000x reference)
#include <cuda_runtime.h>
#include <math.h>

// ---------------- problem constants ----------------
#define BN_    8
#define SN_    4096
#define HIDN   1280
#define CROSSN 768
#define HEADSN 20
#define HDN    64
#define RANKN  128
#define TEXTN  77
#define NIPN   4
#define NFTOKN 16
#define NFACEN 2
#define ENCTN  (TEXTN + NIPN + NFACEN*NFTOKN)   // 113
#define MTOK   (BN_*SN_)                        // 32768
#define HID2N  (2*HIDN)                         // 2560
#define CR2N   (2*CROSSN)                       // 1536

#define SCALE_F 0.125f      // 1/sqrt(64)
#define MIDL_F  0.6f
#define IPS_F   0.6f
#define FIDS_F  0.7f

// ---------------- device scratch (static, allowed) ----------------
__device__ float g_G   [(size_t)MTOK*HID2N];       // gelu(hs@qr_w1^T+b1)
__device__ float g_Q   [(size_t)MTOK*HIDN];        // query
__device__ float g_H   [(size_t)MTOK*HIDN];        // attention combined output
__device__ float g_lq  [(size_t)MTOK*RANKN];
__device__ float g_lo  [(size_t)MTOK*RANKN];
__device__ float g_Xtext[BN_*TEXTN*CROSSN];
__device__ float g_Xip  [BN_*NIPN*CROSSN];
__device__ float g_Xfid [BN_*NFACEN*NFTOKN*CROSSN];
__device__ float g_Kt  [BN_*TEXTN*HIDN];
__device__ float g_Vt  [BN_*TEXTN*HIDN];
__device__ float g_lkt [BN_*TEXTN*RANKN];
__device__ float g_lvt [BN_*TEXTN*RANKN];
__device__ float g_Kip [BN_*NIPN*HIDN];
__device__ float g_Vip [BN_*NIPN*HIDN];
__device__ float g_Kf  [BN_*NFACEN*NFTOKN*HIDN];
__device__ float g_Vf  [BN_*NFACEN*NFTOKN*HIDN];
__device__ float g_ragg[BN_*NFACEN*CROSSN];
__device__ float g_g1  [BN_*NFACEN*CR2N];
__device__ float g_rk  [BN_*NFACEN*HIDN];
__device__ float g_Mrt [BN_*NFACEN*HID2N];
__device__ int   g_route[MTOK];

__device__ __forceinline__ float gelu_f(float x) {
    return 0.5f * x * (1.0f + erff(x * 0.7071067811865476f));
}

// ---------------- SGEMM: C[m,n] = A[m,:K] . W[n,:K] with epilogues ----------------
// EPI 0: C = alpha*acc
// EPI 1: C += alpha*acc
// EPI 2: C = acc + bias[n] + R[m,n]
// EPI 3: C = gelu(acc + bias[n])
// Requirements: K % 16 == 0, N % 128 == 0 (M arbitrary, guarded).
template<int EPI>
__global__ void __launch_bounds__(256, 2)
sgemm_k(const float* __restrict__ A, const float* __restrict__ W,
        float* __restrict__ C, int M, int N, int K, float alpha,
        const float* __restrict__ bias, const float* __restrict__ Rres)
{
    __shared__ __align__(16) float As[16][128];
    __shared__ __align__(16) float Ws[16][128];

    const int tid = threadIdx.x;
    const int n0  = blockIdx.x * 128;
    const int m0  = blockIdx.y * 128;
    const int tx  = tid & 15;
    const int ty  = tid >> 4;
    const int lr  = tid >> 2;          // 0..63
    const int lk  = (tid & 3) << 2;    // 0,4,8,12

    float acc[8][8];
#pragma unroll
    for (int i = 0; i < 8; i++)
#pragma unroll
        for (int j = 0; j < 8; j++) acc[i][j] = 0.f;

    for (int k0 = 0; k0 < K; k0 += 16) {
#pragma unroll
        for (int half = 0; half < 2; half++) {
            const int mrow = lr + half * 64;
            const int m = m0 + mrow;
            float4 va = make_float4(0.f, 0.f, 0.f, 0.f);
            if (m < M) va = *reinterpret_cast<const float4*>(&A[(size_t)m * K + k0 + lk]);
            As[lk + 0][mrow] = va.x;
            As[lk + 1][mrow] = va.y;
            As[lk + 2][mrow] = va.z;
            As[lk + 3][mrow] = va.w;
            const int n = n0 + mrow;   // N % 128 == 0 -> always valid
            float4 vw = *reinterpret_cast<const float4*>(&W[(size_t)n * K + k0 + lk]);
            Ws[lk + 0][mrow] = vw.x;
            Ws[lk + 1][mrow] = vw.y;
            Ws[lk + 2][mrow] = vw.z;
            Ws[lk + 3][mrow] = vw.w;
        }
        __syncthreads();
#pragma unroll
        for (int kk = 0; kk < 16; kk++) {
            const float4* Ak = reinterpret_cast<const float4*>(As[kk]);
            const float4* Wk = reinterpret_cast<const float4*>(Ws[kk]);
            float4 a0 = Ak[ty * 2 + 0];
            float4 a1 = Ak[ty * 2 + 1];
            float4 b0 = Wk[tx * 2 + 0];
            float4 b1 = Wk[tx * 2 + 1];
            float av[8] = {a0.x, a0.y, a0.z, a0.w, a1.x, a1.y, a1.z, a1.w};
            float bv[8] = {b0.x, b0.y, b0.z, b0.w, b1.x, b1.y, b1.z, b1.w};
#pragma unroll
            for (int i = 0; i < 8; i++)
#pragma unroll
                for (int j = 0; j < 8; j++)
                    acc[i][j] = fmaf(av[i], bv[j], acc[i][j]);
        }
        __syncthreads();
    }

#pragma unroll
    for (int i = 0; i < 8; i++) {
        const int m = m0 + ty * 8 + i;
        if (m >= M) continue;
        const size_t rowbase = (size_t)m * N + n0 + tx * 8;
#pragma unroll
        for (int j = 0; j < 8; j++) {
            const int n = n0 + tx * 8 + j;
            float v;
            if (EPI == 0)      v = alpha * acc[i][j];
            else if (EPI == 1) v = C[rowbase + j] + alpha * acc[i][j];
            else if (EPI == 2) v = acc[i][j] + bias[n] + Rres[rowbase + j];
            else               v = gelu_f(acc[i][j] + bias[n]);
            C[rowbase + j] = v;
        }
    }
}

// ---------------- gather encoder rows into packed buffers ----------------
__global__ void gather_k(const float* __restrict__ enc)
{
    int idx = blockIdx.x * 256 + threadIdx.x;
    if (idx >= BN_ * ENCTN * CROSSN) return;
    int c = idx % CROSSN;
    int row = idx / CROSSN;
    int b = row / ENCTN, t = row % ENCTN;
    float v = enc[idx];
    if (t < TEXTN)
        g_Xtext[(b * TEXTN + t) * CROSSN + c] = v;
    else if (t < TEXTN + NIPN)
        g_Xip[(b * NIPN + (t - TEXTN)) * CROSSN + c] = v;
    else
        g_Xfid[(b * NFACEN * NFTOKN + (t - TEXTN - NIPN)) * CROSSN + c] = v;
}

// ---------------- face aggregation: r_agg[bf,c] = sum_t fid[bf*16+t,c]*w[t] + b ----------------
__global__ void ragg_k(const float* __restrict__ aggr_w, const float* __restrict__ aggr_b)
{
    const int bf = blockIdx.x;
    const float bb = aggr_b[0];
    for (int c = threadIdx.x; c < CROSSN; c += 256) {
        float s = bb;
#pragma unroll
        for (int t = 0; t < NFTOKN; t++)
            s = fmaf(g_Xfid[(bf * NFTOKN + t) * CROSSN + c], aggr_w[t], s);
        g_ragg[bf * CROSSN + c] = s;
    }
}

// ---------------- M[bf,j] = sum_d rk[bf,d] * qr_w2[d,j]  (router fold) ----------------
__global__ void __launch_bounds__(256) mker(const float* __restrict__ qr_w2)
{
    __shared__ float rks[HIDN];
    const int bf = blockIdx.x;
    for (int d = threadIdx.x; d < HIDN; d += 256) rks[d] = g_rk[bf * HIDN + d];
    __syncthreads();
    const int j = blockIdx.y * 256 + threadIdx.x;
    float s = 0.f;
#pragma unroll 8
    for (int d = 0; d < HIDN; d++)
        s = fmaf(rks[d], qr_w2[(size_t)d * HID2N + j], s);
    g_Mrt[bf * HID2N + j] = s;
}

// ---------------- routing: warp per token, logits argmax ----------------
__global__ void __launch_bounds__(256) route_k()
{
    const int token = blockIdx.x * 8 + (threadIdx.x >> 5);
    const int lane = threadIdx.x & 31;
    const int b = token >> 12;  // /4096
    const float4* g4 = reinterpret_cast<const float4*>(&g_G[(size_t)token * HID2N]);
    const float4* m0 = reinterpret_cast<const float4*>(&g_Mrt[(b * 2 + 0) * HID2N]);
    const float4* m1 = reinterpret_cast<const float4*>(&g_Mrt[(b * 2 + 1) * HID2N]);
    float a0 = 0.f, a1 = 0.f;
    for (int i = lane; i < HID2N / 4; i += 32) {
        float4 g = g4[i], x = m0[i], y = m1[i];
        a0 += g.x * x.x + g.y * x.y + g.z * x.z + g.w * x.w;
        a1 += g.x * y.x + g.y * y.y + g.z * y.z + g.w * y.w;
    }
#pragma unroll
    for (int o = 16; o > 0; o >>= 1) {
        a0 += __shfl_down_sync(0xffffffffu, a0, o);
        a1 += __shfl_down_sync(0xffffffffu, a1, o);
    }
    if (lane == 0) g_route[token] = (a1 > a0) ? 1 : 0;
}

// ---------------- attention segment: online softmax over nk keys ----------------
__device__ __forceinline__ void attn_seg(const float* ks, const float* vs, int nk,
                                         const float (&q)[64], float (&acc)[64], float& l_out)
{
    float m = -INFINITY, l = 0.f;
#pragma unroll
    for (int d = 0; d < 64; d++) acc[d] = 0.f;
    for (int j = 0; j < nk; j++) {
        const float4* k4 = reinterpret_cast<const float4*>(ks + (j << 6));
        float s = 0.f;
#pragma unroll
        for (int i = 0; i < 16; i++) {
            float4 kk = k4[i];
            s = fmaf(q[4 * i + 0], kk.x, s);
            s = fmaf(q[4 * i + 1], kk.y, s);
            s = fmaf(q[4 * i + 2], kk.z, s);
            s = fmaf(q[4 * i + 3], kk.w, s);
        }
        s *= SCALE_F;
        const float4* v4 = reinterpret_cast<const float4*>(vs + (j << 6));
        if (s > m) {
            const float corr = expf(m - s);   // first iter: exp(-inf)=0
            l = l * corr + 1.f;
#pragma unroll
            for (int i = 0; i < 16; i++) {
                float4 vv = v4[i];
                acc[4 * i + 0] = fmaf(acc[4 * i + 0], corr, vv.x);
                acc[4 * i + 1] = fmaf(acc[4 * i + 1], corr, vv.y);
                acc[4 * i + 2] = fmaf(acc[4 * i + 2], corr, vv.z);
                acc[4 * i + 3] = fmaf(acc[4 * i + 3], corr, vv.w);
            }
            m = s;
        } else {
            const float p = expf(s - m);
            l += p;
#pragma unroll
            for (int i = 0; i < 16; i++) {
                float4 vv = v4[i];
                acc[4 * i + 0] = fmaf(p, vv.x, acc[4 * i + 0]);
                acc[4 * i + 1] = fmaf(p, vv.y, acc[4 * i + 1]);
                acc[4 * i + 2] = fmaf(p, vv.z, acc[4 * i + 2]);
                acc[4 * i + 3] = fmaf(p, vv.w, acc[4 * i + 3]);
            }
        }
    }
    l_out = l;
}

// ---------------- attention: grid (S/128, HEADS, B), 1 thread = 1 query row ----------------
__global__ void __launch_bounds__(128, 1) attn_k()
{
    __shared__ __align__(16) float smbuf[TEXTN * HDN * 2];  // 38.5 KB, reused for phase 2

    const int h = blockIdx.y, b = blockIdx.z, tid = threadIdx.x;
    const int hc = h * HDN;
    const int s = blockIdx.x * 128 + tid;
    const size_t qbase = (size_t)(b * SN_ + s) * HIDN + hc;

    // phase 1: text K/V
    float* kt = smbuf;
    float* vt = smbuf + TEXTN * HDN;
    for (int i = tid; i < TEXTN * HDN; i += 128) {
        int r = i >> 6, c = i & 63;
        size_t g = (size_t)(b * TEXTN + r) * HIDN + hc + c;
        kt[i] = g_Kt[g];
        vt[i] = g_Vt[g];
    }
    __syncthreads();

    float q[64];
#pragma unroll
    for (int i = 0; i < 16; i++) {
        float4 v4 = *reinterpret_cast<const float4*>(&g_Q[qbase + i * 4]);
        q[4 * i + 0] = v4.x; q[4 * i + 1] = v4.y; q[4 * i + 2] = v4.z; q[4 * i + 3] = v4.w;
    }

    float out[64], acc[64], l;
    attn_seg(kt, vt, TEXTN, q, acc, l);
    float wgt = 1.f / l;
#pragma unroll
    for (int d = 0; d < 64; d++) out[d] = acc[d] * wgt;
    __syncthreads();   // everyone done with phase-1 smem

    // phase 2: ip + face K/V
    float* kip = smbuf;
    float* vip = smbuf + NIPN * HDN;                       // +256
    float* kf  = smbuf + 2 * NIPN * HDN;                   // +512
    float* vf  = kf + NFACEN * NFTOKN * HDN;               // +2048
    for (int i = tid; i < NIPN * HDN; i += 128) {
        int r = i >> 6, c = i & 63;
        size_t g = (size_t)(b * NIPN + r) * HIDN + hc + c;
        kip[i] = g_Kip[g];
        vip[i] = g_Vip[g];
    }
    for (int i = tid; i < NFACEN * NFTOKN * HDN; i += 128) {
        int r = i >> 6, c = i & 63;
        size_t g = (size_t)(b * NFACEN * NFTOKN + r) * HIDN + hc + c;
        kf[i] = g_Kf[g];
        vf[i] = g_Vf[g];
    }
    __syncthreads();

    attn_seg(kip, vip, NIPN, q, acc, l);
    wgt = IPS_F / l;
#pragma unroll
    for (int d = 0; d < 64; d++) out[d] = fmaf(acc[d], wgt, out[d]);

    const int face = g_route[b * SN_ + s];
    attn_seg(kf + face * (NFTOKN * HDN), vf + face * (NFTOKN * HDN), NFTOKN, q, acc, l);
    wgt = FIDS_F / l;
#pragma unroll
    for (int d = 0; d < 64; d++) out[d] = fmaf(acc[d], wgt, out[d]);

#pragma unroll
    for (int i = 0; i < 16; i++) {
        float4 v4 = make_float4(out[4 * i], out[4 * i + 1], out[4 * i + 2], out[4 * i + 3]);
        *reinterpret_cast<float4*>(&g_H[qbase + i * 4]) = v4;
    }
}

// ---------------- host ----------------
static dim3 ggrid(int M, int N) { return dim3((N + 127) / 128, (M + 127) / 128); }

extern "C" void kernel_launch(void* const* d_in, const int* in_sizes, int n_in,
                              void* d_out, int out_size)
{
    (void)in_sizes; (void)n_in; (void)out_size;
    const float* hs     = (const float*)d_in[0];
    const float* enc    = (const float*)d_in[1];
    const float* wq     = (const float*)d_in[2];
    const float* wk     = (const float*)d_in[3];
    const float* wv     = (const float*)d_in[4];
    const float* wo     = (const float*)d_in[5];
    const float* bo     = (const float*)d_in[6];
    const float* q_ld   = (const float*)d_in[7];
    const float* q_lu   = (const float*)d_in[8];
    const float* k_ld   = (const float*)d_in[9];
    const float* k_lu   = (const float*)d_in[10];
    const float* v_ld   = (const float*)d_in[11];
    const float* v_lu   = (const float*)d_in[12];
    const float* o_ld   = (const float*)d_in[13];
    const float* o_lu   = (const float*)d_in[14];
    const float* wk_ip  = (const float*)d_in[15];
    const float* wv_ip  = (const float*)d_in[16];
    const float* wk_fid = (const float*)d_in[17];
    const float* wv_fid = (const float*)d_in[18];
    const float* qr_w1  = (const float*)d_in[19];
    const float* qr_b1  = (const float*)d_in[20];
    const float* qr_w2  = (const float*)d_in[21];
    const float* kr_w1  = (const float*)d_in[22];
    const float* kr_b1  = (const float*)d_in[23];
    const float* kr_w2  = (const float*)d_in[24];
    const float* aggr_w = (const float*)d_in[25];
    const float* aggr_b = (const float*)d_in[26];
    float* out = (float*)d_out;

    void* p;
    float *pG, *pQ, *pH, *plq, *plo, *pXt, *pXip, *pXf, *pKt, *pVt, *plkt, *plvt,
          *pKip, *pVip, *pKf, *pVf, *pra, *pg1, *prk;
    cudaGetSymbolAddress(&p, g_G);     pG   = (float*)p;
    cudaGetSymbolAddress(&p, g_Q);     pQ   = (float*)p;
    cudaGetSymbolAddress(&p, g_H);     pH   = (float*)p;
    cudaGetSymbolAddress(&p, g_lq);    plq  = (float*)p;
    cudaGetSymbolAddress(&p, g_lo);    plo  = (float*)p;
    cudaGetSymbolAddress(&p, g_Xtext); pXt  = (float*)p;
    cudaGetSymbolAddress(&p, g_Xip);   pXip = (float*)p;
    cudaGetSymbolAddress(&p, g_Xfid);  pXf  = (float*)p;
    cudaGetSymbolAddress(&p, g_Kt);    pKt  = (float*)p;
    cudaGetSymbolAddress(&p, g_Vt);    pVt  = (float*)p;
    cudaGetSymbolAddress(&p, g_lkt);   plkt = (float*)p;
    cudaGetSymbolAddress(&p, g_lvt);   plvt = (float*)p;
    cudaGetSymbolAddress(&p, g_Kip);   pKip = (float*)p;
    cudaGetSymbolAddress(&p, g_Vip);   pVip = (float*)p;
    cudaGetSymbolAddress(&p, g_Kf);    pKf  = (float*)p;
    cudaGetSymbolAddress(&p, g_Vf);    pVf  = (float*)p;
    cudaGetSymbolAddress(&p, g_ragg);  pra  = (float*)p;
    cudaGetSymbolAddress(&p, g_g1);    pg1  = (float*)p;
    cudaGetSymbolAddress(&p, g_rk);    prk  = (float*)p;

    // --- encoder-side prep ---
    gather_k<<<(BN_ * ENCTN * CROSSN + 255) / 256, 256>>>(enc);
    ragg_k<<<BN_ * NFACEN, 256>>>(aggr_w, aggr_b);
    sgemm_k<3><<<ggrid(BN_ * NFACEN, CR2N), 256>>>(pra, kr_w1, pg1, BN_ * NFACEN, CR2N, CROSSN, 1.f, kr_b1, nullptr);
    sgemm_k<0><<<ggrid(BN_ * NFACEN, HIDN), 256>>>(pg1, kr_w2, prk, BN_ * NFACEN, HIDN, CR2N, 1.f, nullptr, nullptr);
    mker<<<dim3(BN_ * NFACEN, HID2N / 256), 256>>>(qr_w2);

    // --- text K/V (with LoRA) ---
    const int Mt = BN_ * TEXTN;
    sgemm_k<0><<<ggrid(Mt, RANKN), 256>>>(pXt, k_ld, plkt, Mt, RANKN, CROSSN, 1.f, nullptr, nullptr);
    sgemm_k<0><<<ggrid(Mt, HIDN), 256>>>(pXt, wk, pKt, Mt, HIDN, CROSSN, 1.f, nullptr, nullptr);
    sgemm_k<1><<<ggrid(Mt, HIDN), 256>>>(plkt, k_lu, pKt, Mt, HIDN, RANKN, MIDL_F, nullptr, nullptr);
    sgemm_k<0><<<ggrid(Mt, RANKN), 256>>>(pXt, v_ld, plvt, Mt, RANKN, CROSSN, 1.f, nullptr, nullptr);
    sgemm_k<0><<<ggrid(Mt, HIDN), 256>>>(pXt, wv, pVt, Mt, HIDN, CROSSN, 1.f, nullptr, nullptr);
    sgemm_k<1><<<ggrid(Mt, HIDN), 256>>>(plvt, v_lu, pVt, Mt, HIDN, RANKN, MIDL_F, nullptr, nullptr);

    // --- ip / face K,V ---
    sgemm_k<0><<<ggrid(BN_ * NIPN, HIDN), 256>>>(pXip, wk_ip, pKip, BN_ * NIPN, HIDN, CROSSN, 1.f, nullptr, nullptr);
    sgemm_k<0><<<ggrid(BN_ * NIPN, HIDN), 256>>>(pXip, wv_ip, pVip, BN_ * NIPN, HIDN, CROSSN, 1.f, nullptr, nullptr);
    sgemm_k<0><<<ggrid(BN_ * NFACEN * NFTOKN, HIDN), 256>>>(pXf, wk_fid, pKf, BN_ * NFACEN * NFTOKN, HIDN, CROSSN, 1.f, nullptr, nullptr);
    sgemm_k<0><<<ggrid(BN_ * NFACEN * NFTOKN, HIDN), 256>>>(pXf, wv_fid, pVf, BN_ * NFACEN * NFTOKN, HIDN, CROSSN, 1.f, nullptr, nullptr);

    // --- query projection (with LoRA) ---
    sgemm_k<0><<<ggrid(MTOK, RANKN), 256>>>(hs, q_ld, plq, MTOK, RANKN, HIDN, 1.f, nullptr, nullptr);
    sgemm_k<0><<<ggrid(MTOK, HIDN), 256>>>(hs, wq, pQ, MTOK, HIDN, HIDN, 1.f, nullptr, nullptr);
    sgemm_k<1><<<ggrid(MTOK, HIDN), 256>>>(plq, q_lu, pQ, MTOK, HIDN, RANKN, MIDL_F, nullptr, nullptr);

    // --- router: G = gelu(hs@qr_w1^T + b1); logits folded through M; argmax ---
    sgemm_k<3><<<ggrid(MTOK, HID2N), 256>>>(hs, qr_w1, pG, MTOK, HID2N, HIDN, 1.f, qr_b1, nullptr);
    route_k<<<MTOK / 8, 256>>>();

    // --- attention (text + ip + routed face), writes g_H ---
    attn_k<<<dim3(SN_ / 128, HEADSN, BN_), 128>>>();

    // --- output projection (with LoRA) + bias + residual ---
    sgemm_k<0><<<ggrid(MTOK, RANKN), 256>>>(pH, o_ld, plo, MTOK, RANKN, HIDN, 1.f, nullptr, nullptr);
    sgemm_k<2><<<ggrid(MTOK, HIDN), 256>>>(pH, wo, out, MTOK, HIDN, HIDN, 1.f, bo, hs);
    sgemm_k<1><<<ggrid(MTOK, HIDN), 256>>>(plo, o_lu, out, MTOK, HIDN, RANKN, MIDL_F, nullptr, nullptr);
}